// round 8
// baseline (speedup 1.0000x reference)
#include <cuda_runtime.h>
#include <cstdint>

#define BB      48
#define NKC     800
#define NMBON   20
#define NFBN    60
#define NDAN    20
#define NREC    100
#define TT      121
#define NSTEP   120
#define W_MAXC  0.05f

#define NTHREADS 512
#define NCTA     (BB * 2)

__device__ float g_rkcT[(long)BB * TT * NKC];

// ---------------------------------------------------------------------------
__global__ void transpose_kernel(const float* __restrict__ rkc) {
    __shared__ float tile[32][33];
    const int bz = blockIdx.z;
    const int kt = blockIdx.y;
    const int tt = blockIdx.x;
    const int tx = threadIdx.x, ty = threadIdx.y;

    int k = kt * 32 + ty;
    int t = tt * 32 + tx;
    if (t < TT)
        tile[ty][tx] = rkc[((long)bz * NKC + k) * TT + t];
    __syncthreads();
    int t2 = tt * 32 + ty;
    int k2 = kt * 32 + tx;
    if (t2 < TT)
        g_rkcT[((long)bz * TT + t2) * NKC + k2] = tile[tx][ty];
}

// ---------------------------------------------------------------------------
// 2-CTA cluster per batch (m-split). 512 threads.
// Owners: warps 0-11 (384 thr). g = tid/192 picks 5 rows; c = tid%192 picks
//   float4 chunk k=4c; threads with c%6==0 also own scalar k=768+c/6.
// C-side: warps 12..15 (one per SMSP).
//   w12: i=lane (mbon 0-19 + fbn 20-31), senders & peer-waiters, readout.
//   w13: i=32+lane. w14 lanes<16: i=64+lane. [all dots of step t]
//   after bar.sync(1,128): w14 lanes>=16: DAN i=64+lane (80..95);
//   w15 lanes<4: DAN i=96+lane; w15 lanes>=4: staging (cp ring, rbkc, ifbn).
// One __syncthreads per step.
// ---------------------------------------------------------------------------
// smem (floats): mbar 4 | imb 40 | WrM 10000 | rkc4 3200 | rbkc 1600 | r 200 |
//   bias 100 | ifbn 128 | red 120 | rdan 40 | rbdan 40 | wro 20 | wext 120
#define SM_FLOATS 15612

__global__ __launch_bounds__(NTHREADS, 1) __cluster_dims__(2, 1, 1)
void rnn_kernel(
    const float* __restrict__ r_ext,
    const float* __restrict__ time_arr,
    const float* __restrict__ W_kc0,
    const float* __restrict__ wt0,
    const float* __restrict__ W_recur,
    const float* __restrict__ W_readout,
    const float* __restrict__ bias,
    const float* __restrict__ W_ext,
    float* __restrict__ out)
{
    extern __shared__ float sm[];
    float* mbar_f  = sm;                    // 4
    float* imb     = sm + 4;                // 2 x 20
    float* WrM     = sm + 44;               // 100 x 100 row-major
    float* rkc4    = sm + 10044;            // 4 x 800 ring
    float* rbkc    = sm + 13244;            // 2 x 800
    float* r_s     = sm + 14844;            // 2 x 100
    float* bias_s  = sm + 15044;            // 100
    float* ifbn    = sm + 15144;            // 2 x 64
    float* red_s   = sm + 15272;            // 2 x 12 x 5
    float* rdan_s  = sm + 15392;            // 2 x 20
    float* rbdan_s = sm + 15432;            // 2 x 20
    float* wro_s   = sm + 15472;            // 20
    float* wext_s  = sm + 15492;            // 120

    const int tid  = threadIdx.x;
    const int bx   = blockIdx.x;
    const int b    = bx >> 1;
    const int rank = bx & 1;
    const int prank = rank ^ 1;
    const int m_off = rank * 10;
    const int lane = tid & 31;
    const int warp = tid >> 5;

    const bool is_owner = (warp < 12);
    const int  g  = tid / 192;              // row group (owners)
    const int  c  = tid % 192;              // k chunk
    const bool has_ex = is_owner && (c % 6 == 0);
    const int  ke = 768 + c / 6;            // extra scalar k

    float* out_r  = out;
    float* out_W  = out + (long)TT * BB * NREC;
    float* out_wt = out_W + (long)TT * BB * NMBON * NKC;
    float* out_ro = out_wt + (long)TT * BB * NMBON * NKC;

    const float dt  = time_arr[1] - time_arr[0];
    const float a_r = dt;
    const float a_w = dt * 0.2f;

    const float* rkc_g = g_rkcT + (long)b * TT * NKC;

    const uint32_t imb_loc  = (uint32_t)__cvta_generic_to_shared(imb);
    const uint32_t mbar_loc = (uint32_t)__cvta_generic_to_shared(mbar_f);
    uint32_t imb_rem, mbar_rem;
    asm("mapa.shared::cluster.u32 %0, %1, %2;" : "=r"(imb_rem)  : "r"(imb_loc),  "r"(prank));
    asm("mapa.shared::cluster.u32 %0, %1, %2;" : "=r"(mbar_rem) : "r"(mbar_loc), "r"(prank));

    // ---------------- init ----------------
    if (tid == 0) {
        asm volatile("mbarrier.init.shared.b64 [%0], 10;" :: "r"(mbar_loc)     : "memory");
        asm volatile("mbarrier.init.shared.b64 [%0], 10;" :: "r"(mbar_loc + 8) : "memory");
    }
    for (int idx = tid; idx < NREC * NREC; idx += NTHREADS) {
        int i = idx / NREC, j = idx % NREC;
        float v = W_recur[idx];
        if (i < NMBON && j >= NREC - NDAN) v = 0.f;
        WrM[idx] = v;
    }
    if (tid < NREC)  bias_s[tid] = bias[tid];
    if (tid < NMBON) wro_s[tid]  = W_readout[tid];
    if (tid >= 128 && tid < 128 + NFBN * 2) wext_s[tid - 128] = W_ext[tid - 128];
    if (tid < NREC) {
        float r0 = (tid < NMBON) ? 0.f : 0.1f;
        r_s[tid] = r0;
        if (rank == 0) out_r[(long)b * NREC + tid] = r0;
    }
    for (int k = tid; k < NKC; k += NTHREADS) {
        float v = rkc_g[k];
        rkc4[k] = v;            // ring slot 0 = rkc(0)
        rbkc[k] = v;            // rb_kc(after step-0 update) == rkc(0)
    }
    __syncthreads();            // wext ready
    if (tid < NFBN) {
        float e0 = r_ext[((long)b * 2 + 0) * TT];
        float e1 = r_ext[((long)b * 2 + 1) * TT];
        ifbn[tid] = wext_s[tid * 2] * e0 + wext_s[tid * 2 + 1] * e1;
    }
    if (tid == 0 && rank == 0) out_ro[b] = 0.f;

    // owner state
    float4 Wv[5], wtv[5];
    float  Wex[5], wtex[5];
    if (is_owner) {
        const long ibase = ((long)b * NMBON + m_off + g * 5) * NKC;
        const long obase = ((long)b) * (NMBON * NKC) + (long)(m_off + g * 5) * NKC;
#pragma unroll
        for (int mm = 0; mm < 5; ++mm) {
            float4 w  = *(const float4*)(W_kc0 + ibase + (long)mm * NKC + c * 4);
            float4 wt = *(const float4*)(wt0   + ibase + (long)mm * NKC + c * 4);
            Wv[mm] = w; wtv[mm] = wt;
            *(float4*)(out_W  + obase + (long)mm * NKC + c * 4) = w;
            *(float4*)(out_wt + obase + (long)mm * NKC + c * 4) = wt;
            if (has_ex) {
                Wex[mm]  = W_kc0[ibase + (long)mm * NKC + ke];
                wtex[mm] = wt0  [ibase + (long)mm * NKC + ke];
                out_W [obase + (long)mm * NKC + ke] = Wex[mm];
                out_wt[obase + (long)mm * NKC + ke] = wtex[mm];
            } else { Wex[mm] = 0.f; wtex[mm] = 0.f; }
        }
    } else {
#pragma unroll
        for (int mm = 0; mm < 5; ++mm) {
            Wv[mm] = make_float4(0.f,0.f,0.f,0.f); wtv[mm] = Wv[mm];
            Wex[mm] = 0.f; wtex[mm] = 0.f;
        }
    }
    __syncthreads();            // r_s, rkc4[0], bias ready

    // ---- pre-loop: B(0) ∥ DAN(0) ∥ cp prefetch slots 1,2 ----
    float rb_reg = 0.1f;        // DAN threads' rbdan carry
    if (is_owner) {
        float4 kc = *(const float4*)(rkc4 + c * 4);
        float kce = has_ex ? rkc4[ke] : 0.f;
#pragma unroll
        for (int mm = 0; mm < 5; ++mm) {
            float4 w = Wv[mm];
            float p = w.x*kc.x + w.y*kc.y + w.z*kc.z + w.w*kc.w + Wex[mm]*kce;
            p += __shfl_xor_sync(0xffffffffu, p, 16);
            p += __shfl_xor_sync(0xffffffffu, p, 8);
            p += __shfl_xor_sync(0xffffffffu, p, 4);
            p += __shfl_xor_sync(0xffffffffu, p, 2);
            p += __shfl_xor_sync(0xffffffffu, p, 1);
            if (lane == 0) red_s[warp * 5 + mm] = p;   // parity 0
        }
    } else {
        int dan_i = -1;
        if (warp == 14 && lane >= 16) dan_i = 64 + lane;       // 80..95
        if (warp == 15 && lane < 4)   dan_i = 96 + lane;       // 96..99
        if (dan_i >= 0) {
            const float4* wrow = (const float4*)(WrM + dan_i * NREC);
            const float4* r4   = (const float4*)r_s;           // r(0) in buf 0
            float a0=0.f,a1=0.f,a2=0.f,a3=0.f;
#pragma unroll
            for (int jb = 0; jb < 25; ++jb) {
                float4 wv = wrow[jb]; float4 rv = r4[jb];
                a0 = fmaf(wv.x, rv.x, a0); a1 = fmaf(wv.y, rv.y, a1);
                a2 = fmaf(wv.z, rv.z, a2); a3 = fmaf(wv.w, rv.w, a3);
            }
            float pre  = (a0+a1)+(a2+a3) + bias_s[dan_i];
            float rold = r_s[dan_i];
            float rn   = fmaf(a_r, fmaxf(pre, 0.f) - rold, rold);
            r_s[100 + dan_i] = rn;                              // r(1)[dan] in buf 1
            if (rank == 0) out_r[((long)1 * BB + b) * NREC + dan_i] = rn;
            int m = dan_i - 80;
            rdan_s[m] = rn;                                     // parity 0
            rb_reg = fmaf(a_w, rn - rb_reg, rb_reg);
            rbdan_s[m] = rb_reg;
        }
        if (warp == 15 && lane >= 4) {
            // prefetch rkc(1)->slot1 (group), rkc(2)->slot2 (group)
            int sl = lane - 4;
#pragma unroll
            for (int u = 1; u <= 2; ++u) {
                const float* gsrc = rkc_g + (long)u * NKC;
#pragma unroll
                for (int j = 0; j < 8; ++j) {
                    int ci = sl + 28 * j;
                    if (ci < 200) {
                        uint32_t dst = (uint32_t)__cvta_generic_to_shared(rkc4 + u * 800 + ci * 4);
                        asm volatile("cp.async.cg.shared.global [%0], [%1], 16;\n"
                                     :: "r"(dst), "l"(gsrc + ci * 4));
                    }
                }
                asm volatile("cp.async.commit_group;\n" ::: "memory");
            }
            asm volatile("cp.async.wait_group 1;\n" ::: "memory");   // slot1 done
        }
    }
    __syncthreads();
    asm volatile("barrier.cluster.arrive.aligned;" ::: "memory");
    asm volatile("barrier.cluster.wait.aligned;"   ::: "memory");

    // ---------------- time loop: ONE barrier per step ----------------
    for (int t = 0; t < NSTEP; ++t) {
        const int hb  = t & 1;
        const int par = (t >> 1) & 1;
        const int s0  = t & 3;              // ring slot for rkc(t)
        const int s1  = (t + 1) & 3;

        if (is_owner) {
            // ---- D(t): plasticity + streaming stores ----
            float4 kc = *(const float4*)(rkc4 + s0 * 800 + c * 4);
            float4 bk = *(const float4*)(rbkc + hb * 800 + c * 4);
            float kce = 0.f, bke = 0.f;
            if (has_ex) { kce = rkc4[s0 * 800 + ke]; bke = rbkc[hb * 800 + ke]; }
            const long obase = ((long)(t + 1) * BB + b) * (NMBON * NKC)
                             + (long)(m_off + g * 5) * NKC;
#pragma unroll
            for (int mm = 0; mm < 5; ++mm) {
                const int m = m_off + g * 5 + mm;
                const float rbd = rbdan_s[hb * 20 + m];
                const float rd  = rdan_s[hb * 20 + m];
                float4 w = Wv[mm], wt = wtv[mm];
                float dw;
                dw = fmaf(rbd, kc.x, -(rd * bk.x)); wt.x = fmaf(dw, dt, wt.x);
                dw = fmaf(rbd, kc.y, -(rd * bk.y)); wt.y = fmaf(dw, dt, wt.y);
                dw = fmaf(rbd, kc.z, -(rd * bk.z)); wt.z = fmaf(dw, dt, wt.z);
                dw = fmaf(rbd, kc.w, -(rd * bk.w)); wt.w = fmaf(dw, dt, wt.w);
                w.x = fminf(fmaxf(fmaf(a_w, wt.x - w.x, w.x), 0.f), W_MAXC);
                w.y = fminf(fmaxf(fmaf(a_w, wt.y - w.y, w.y), 0.f), W_MAXC);
                w.z = fminf(fmaxf(fmaf(a_w, wt.z - w.z, w.z), 0.f), W_MAXC);
                w.w = fminf(fmaxf(fmaf(a_w, wt.w - w.w, w.w), 0.f), W_MAXC);
                Wv[mm] = w; wtv[mm] = wt;
                *(float4*)(out_W  + obase + (long)mm * NKC + c * 4) = w;
                *(float4*)(out_wt + obase + (long)mm * NKC + c * 4) = wt;
                if (has_ex) {
                    float dwe = fmaf(rbd, kce, -(rd * bke));
                    wtex[mm] = fmaf(dwe, dt, wtex[mm]);
                    Wex[mm]  = fminf(fmaxf(fmaf(a_w, wtex[mm] - Wex[mm], Wex[mm]), 0.f), W_MAXC);
                    out_W [obase + (long)mm * NKC + ke] = Wex[mm];
                    out_wt[obase + (long)mm * NKC + ke] = wtex[mm];
                }
            }
            // ---- B(t+1) ----
            if (t < NSTEP - 1) {
                float4 kc1 = *(const float4*)(rkc4 + s1 * 800 + c * 4);
                float kce1 = has_ex ? rkc4[s1 * 800 + ke] : 0.f;
#pragma unroll
                for (int mm = 0; mm < 5; ++mm) {
                    float4 w = Wv[mm];
                    float p = w.x*kc1.x + w.y*kc1.y + w.z*kc1.z + w.w*kc1.w + Wex[mm]*kce1;
                    p += __shfl_xor_sync(0xffffffffu, p, 16);
                    p += __shfl_xor_sync(0xffffffffu, p, 8);
                    p += __shfl_xor_sync(0xffffffffu, p, 4);
                    p += __shfl_xor_sync(0xffffffffu, p, 2);
                    p += __shfl_xor_sync(0xffffffffu, p, 1);
                    if (lane == 0) red_s[((t + 1) & 1) * 60 + warp * 5 + mm] = p;
                }
            }
        } else {
            // ================= C-side =================
            const float* rc = r_s + hb * NREC;
            float* rn_buf   = r_s + (hb ^ 1) * NREC;

            float vloc = 0.f;
            if (warp == 12) {
                // senders: local mbon rows (lanes m_off..m_off+9)
                int lm = lane - m_off;
                if (lm >= 0 && lm < 10) {
                    const float* rp = red_s + par * 0 + hb * 60;   // red parity = t&1
                    int base = (lm < 5) ? 0 : 6;
                    int mmofs = (lm < 5) ? lm : lm - 5;
                    vloc = rp[(base + 0) * 5 + mmofs] + rp[(base + 1) * 5 + mmofs]
                         + rp[(base + 2) * 5 + mmofs] + rp[(base + 3) * 5 + mmofs]
                         + rp[(base + 4) * 5 + mmofs] + rp[(base + 5) * 5 + mmofs];
                    asm volatile("st.shared::cluster.f32 [%0], %1;"
                                 :: "r"(imb_rem + (hb * 20 + m_off + lm) * 4), "f"(vloc) : "memory");
                    asm volatile("mbarrier.arrive.release.cluster.shared::cluster.b64 _, [%0];"
                                 :: "r"(mbar_rem + hb * 8) : "memory");
                }
            }

            // dots(t): i = 0..79
            int di = -1;
            if (warp == 12) di = lane;
            else if (warp == 13) di = 32 + lane;
            else if (warp == 14 && lane < 16) di = 64 + lane;

            float rn_val = 0.f;
            if (di >= 0) {
                const float4* wrow = (const float4*)(WrM + di * NREC);
                const float4* r4   = (const float4*)rc;
                float a0=0.f,a1=0.f,a2=0.f,a3=0.f;
#pragma unroll
                for (int jb = 0; jb < 25; ++jb) {
                    float4 wv = wrow[jb]; float4 rv = r4[jb];
                    a0 = fmaf(wv.x, rv.x, a0); a1 = fmaf(wv.y, rv.y, a1);
                    a2 = fmaf(wv.z, rv.z, a2); a3 = fmaf(wv.w, rv.w, a3);
                }
                float p = (a0+a1)+(a2+a3);
                float itot;
                if (di < NMBON) {
                    int lm = di - m_off;
                    if (lm >= 0 && lm < 10) {
                        itot = vloc;
                    } else {
                        uint32_t done;
                        asm volatile(
                            "{\n\t.reg .pred p;\n\t"
                            "mbarrier.try_wait.parity.acquire.cluster.shared::cta.b64 p, [%1], %2;\n\t"
                            "selp.b32 %0, 1, 0, p;\n\t}"
                            : "=r"(done) : "r"(mbar_loc + hb * 8), "r"(par) : "memory");
                        while (!done) {
                            asm volatile(
                                "{\n\t.reg .pred p;\n\t"
                                "mbarrier.try_wait.parity.acquire.cluster.shared::cta.b64 p, [%1], %2, 0x989680;\n\t"
                                "selp.b32 %0, 1, 0, p;\n\t}"
                                : "=r"(done) : "r"(mbar_loc + hb * 8), "r"(par) : "memory");
                        }
                        itot = imb[hb * 20 + di];
                    }
                } else {
                    itot = ifbn[hb * 64 + (di - NMBON)];
                }
                float pre  = p + bias_s[di] + itot;
                float rold = rc[di];
                rn_val = fmaf(a_r, fmaxf(pre, 0.f) - rold, rold);
                rn_buf[di] = rn_val;
                if (rank == 0) out_r[((long)(t + 1) * BB + b) * NREC + di] = rn_val;
            }

            asm volatile("bar.sync 1, 128;" ::: "memory");   // C-side: r(t+1) complete

            if (warp == 12) {
                // readout(t+1)
                float v = (lane < NMBON) ? rn_val * wro_s[lane] : 0.f;
                v += __shfl_xor_sync(0xffffffffu, v, 16);
                v += __shfl_xor_sync(0xffffffffu, v, 8);
                v += __shfl_xor_sync(0xffffffffu, v, 4);
                v += __shfl_xor_sync(0xffffffffu, v, 2);
                v += __shfl_xor_sync(0xffffffffu, v, 1);
                if (lane == 0 && rank == 0) out_ro[(long)(t + 1) * BB + b] = v;
            }

            if (t < NSTEP - 1) {
                // DAN(t+1): i=80..99, from r(t+1) = rn_buf
                int dan_i = -1;
                if (warp == 14 && lane >= 16) dan_i = 64 + lane;
                if (warp == 15 && lane < 4)   dan_i = 96 + lane;
                if (dan_i >= 0) {
                    const float4* wrow = (const float4*)(WrM + dan_i * NREC);
                    const float4* r4   = (const float4*)rn_buf;
                    float a0=0.f,a1=0.f,a2=0.f,a3=0.f;
#pragma unroll
                    for (int jb = 0; jb < 25; ++jb) {
                        float4 wv = wrow[jb]; float4 rv = r4[jb];
                        a0 = fmaf(wv.x, rv.x, a0); a1 = fmaf(wv.y, rv.y, a1);
                        a2 = fmaf(wv.z, rv.z, a2); a3 = fmaf(wv.w, rv.w, a3);
                    }
                    float pre  = (a0+a1)+(a2+a3) + bias_s[dan_i];
                    float rold = rn_buf[dan_i];
                    float rn   = fmaf(a_r, fmaxf(pre, 0.f) - rold, rold);
                    r_s[hb * NREC + dan_i] = rn;      // r(t+2)[dan] -> buffer (t+2)&1 == hb
                    if (rank == 0) out_r[((long)(t + 2) * BB + b) * NREC + dan_i] = rn;
                    int m = dan_i - 80;
                    rdan_s[((t + 1) & 1) * 20 + m] = rn;
                    rb_reg = fmaf(a_w, rn - rb_reg, rb_reg);
                    rbdan_s[((t + 1) & 1) * 20 + m] = rb_reg;
                }
                if (warp == 15 && lane >= 4) {
                    // staging for step t+1: cp rkc(t+3), rbkc(t+1), ifbn(t+1)
                    int sl = lane - 4;
                    if (t + 3 <= NSTEP) {   // rkc index t+3 <= 120
                        const float* gsrc = rkc_g + (long)(t + 3) * NKC;
                        const int s3 = (t + 3) & 3;
#pragma unroll
                        for (int j = 0; j < 8; ++j) {
                            int ci = sl + 28 * j;
                            if (ci < 200) {
                                uint32_t dst = (uint32_t)__cvta_generic_to_shared(rkc4 + s3 * 800 + ci * 4);
                                asm volatile("cp.async.cg.shared.global [%0], [%1], 16;\n"
                                             :: "r"(dst), "l"(gsrc + ci * 4));
                            }
                        }
                        asm volatile("cp.async.commit_group;\n" ::: "memory");
                    }
                    // rb_kc(t+1) = rbkc[hb] + a_w*(rkc(t+1) - rbkc[hb]) -> rbkc[hb^1]
                    float e0 = r_ext[((long)b * 2 + 0) * TT + (t + 1)];
                    float e1 = r_ext[((long)b * 2 + 1) * TT + (t + 1)];
#pragma unroll
                    for (int j = 0; j < 8; ++j) {
                        int ci = sl + 28 * j;
                        if (ci < 200) {
                            float4 kc = *(const float4*)(rkc4 + s1 * 800 + ci * 4);
                            float4 bk = *(const float4*)(rbkc + hb * 800 + ci * 4);
                            bk.x = fmaf(a_w, kc.x - bk.x, bk.x);
                            bk.y = fmaf(a_w, kc.y - bk.y, bk.y);
                            bk.z = fmaf(a_w, kc.z - bk.z, bk.z);
                            bk.w = fmaf(a_w, kc.w - bk.w, bk.w);
                            *(float4*)(rbkc + (hb ^ 1) * 800 + ci * 4) = bk;
                        }
                    }
#pragma unroll
                    for (int j = 0; j < 3; ++j) {
                        int f = sl + 28 * j;
                        if (f < NFBN)
                            ifbn[(hb ^ 1) * 64 + f] = wext_s[f * 2] * e0 + wext_s[f * 2 + 1] * e1;
                    }
                    asm volatile("cp.async.wait_group 1;\n" ::: "memory");
                }
            }
        }
        __syncthreads();   // the ONE global barrier per step
    }

    asm volatile("barrier.cluster.arrive.aligned;" ::: "memory");
    asm volatile("barrier.cluster.wait.aligned;"   ::: "memory");
}

// ---------------------------------------------------------------------------
extern "C" void kernel_launch(void* const* d_in, const int* in_sizes, int n_in,
                              void* d_out, int out_size) {
    const float* r_kc      = (const float*)d_in[0];
    const float* r_ext     = (const float*)d_in[1];
    const float* time_arr  = (const float*)d_in[2];
    const float* W_kc0     = (const float*)d_in[3];
    const float* wt0       = (const float*)d_in[4];
    const float* W_recur   = (const float*)d_in[5];
    const float* W_readout = (const float*)d_in[6];
    const float* bias      = (const float*)d_in[7];
    const float* W_ext     = (const float*)d_in[8];
    float* out = (float*)d_out;

    cudaFuncSetAttribute(rnn_kernel, cudaFuncAttributeMaxDynamicSharedMemorySize,
                         SM_FLOATS * (int)sizeof(float));

    transpose_kernel<<<dim3(4, 25, BB), dim3(32, 32)>>>(r_kc);
    rnn_kernel<<<NCTA, NTHREADS, SM_FLOATS * (int)sizeof(float)>>>(
        r_ext, time_arr, W_kc0, wt0, W_recur, W_readout, bias, W_ext, out);
}